// round 12
// baseline (speedup 1.0000x reference)
#include <cuda_runtime.h>
#include <cuda_bf16.h>
#include <cstdint>

#define NQ 8192
#define NK 8192
#define KEEP 4096

// Concatenated float32 output offsets
#define OFF_COORDS 0
#define OFF_VOX    16384
#define OFF_KIMP   98304
#define OFF_IMP    102400

#define SQRT3 1.7320508075688772f

typedef unsigned long long u64;

// ---- persistent device scratch (allocation-free) ----
__device__ __align__(16) float4 g_keys[2][NK];  // (z,y,x,0) grouped by batch, stable order
__device__ int    g_kcnt[2];
__device__ int    g_qidx[2][NQ];                // query indices grouped by batch, stable
__device__ int    g_qcnt[2];
__device__ int    g_bc[64];                     // per-block batch-0 counts
__device__ __align__(16) u64 g_key64[NQ];       // (float_bits(imp)<<13)|idx : stable sort key

// XLA EmitFastTanh (Eigen ptanh<float>) — exact coefficients, clamp, small-x path.
__device__ __forceinline__ float tanh_xla(float x) {
    float ax = fabsf(x);
    float xc = fminf(fmaxf(x, -7.90531110763549805f), 7.90531110763549805f);
    float x2 = xc * xc;
    float p = fmaf(x2, -2.76076847742355e-16f, 2.00018790482477e-13f);
    p = fmaf(x2, p, -8.60467152213735e-11f);
    p = fmaf(x2, p, 5.12229709037114e-08f);
    p = fmaf(x2, p, 1.48572235717979e-05f);
    p = fmaf(x2, p, 6.37261928875436e-04f);
    p = fmaf(x2, p, 4.89352455891786e-03f);
    p = xc * p;
    float q = fmaf(x2, 1.19825839466702e-06f, 1.18534705686654e-04f);
    q = fmaf(x2, q, 2.26843463243900e-03f);
    q = fmaf(x2, q, 4.89352518554385e-03f);
    float r = p / q;
    return (ax < 0.0004f) ? x : r;
}

// ---- partition phase 1: per-block batch-0 counts (64 blocks x 256 threads) ----
__global__ __launch_bounds__(256) void count_kernel(
    const int4* __restrict__ vc, const float4* __restrict__ keys)
{
    __shared__ int ws[8];
    int b = blockIdx.x, t = threadIdx.x;
    int flag;
    if (b < 32) flag = (keys[b * 256 + t].x == 0.0f) ? 1 : 0;
    else        flag = (vc[(b - 32) * 256 + t].x == 0) ? 1 : 0;
    unsigned bal = __ballot_sync(0xffffffffu, flag);
    if ((t & 31) == 0) ws[t >> 5] = __popc(bal);
    __syncthreads();
    if (t == 0) {
        int s = 0;
        #pragma unroll
        for (int i = 0; i < 8; i++) s += ws[i];
        g_bc[b] = s;
    }
}

// ---- partition phase 2: stable scatter (64 blocks x 256 threads) ----
__global__ __launch_bounds__(256) void scatter_kernel(
    const int4* __restrict__ vc, const float4* __restrict__ keys)
{
    __shared__ int ws[8];
    __shared__ int s_pre0, s_tot0;
    int b = blockIdx.x, t = threadIdx.x;
    bool isKey = (b < 32);
    int c = isKey ? b : b - 32;
    int grp = isKey ? 0 : 32;

    if (t < 32) {
        int v = g_bc[grp + t];
        int x = v;
        #pragma unroll
        for (int o = 1; o < 32; o <<= 1) {
            int y = __shfl_up_sync(0xffffffffu, x, o);
            if (t >= o) x += y;
        }
        if (t == c)  s_pre0 = x - v;
        if (t == 31) s_tot0 = x;
    }
    __syncthreads();

    int i = c * 256 + t;
    int flag;
    float4 kv; int4 qv;
    if (isKey) { kv = keys[i]; flag = (kv.x == 0.0f) ? 1 : 0; }
    else       { qv = vc[i];   flag = (qv.x == 0) ? 1 : 0; }

    unsigned bal = __ballot_sync(0xffffffffu, flag);
    int lane = t & 31, w = t >> 5;
    int lpre = __popc(bal & ((1u << lane) - 1u));
    if (lane == 0) ws[w] = __popc(bal);
    __syncthreads();
    int wpre = 0;
    for (int j = 0; j < w; j++) wpre += ws[j];

    int pos0 = s_pre0 + wpre + lpre;
    int pos1 = i - pos0;
    if (isKey) {
        int bb = flag ? 0 : 1;
        int pp = flag ? pos0 : pos1;
        g_keys[bb][pp] = make_float4(kv.y, kv.z, kv.w, 0.0f);  // (z,y,x)
        if (t == 0 && c == 0) { g_kcnt[0] = s_tot0; g_kcnt[1] = NK - s_tot0; }
    } else {
        if (flag) g_qidx[0][pos0] = i; else g_qidx[1][pos1] = i;
        if (t == 0 && c == 0) { g_qcnt[0] = s_tot0; g_qcnt[1] = NQ - s_tot0; }
    }
}

// ---- attention: query-per-lane, key-broadcast, 8 key-chunks per block ----
// Block = 32 same-batch queries (one per lane). Warp w sweeps key chunk w.
// Partials combined via smem in fixed warp order (deterministic).
#define DOTB(k) (fmaf(qx, (k).z, fmaf(qy, (k).y, qz * (k).x)))

__global__ __launch_bounds__(256) void attn_kernel(
    const int4*  __restrict__ vc,
    const float* __restrict__ w1,
    const float* __restrict__ b1,
    const float* __restrict__ w2,
    const float* __restrict__ b2,
    float*       __restrict__ imp_out)
{
    __shared__ float  smax[8][32];
    __shared__ float4 sacc[8][32];

    int warp = threadIdx.x >> 5, lane = threadIdx.x & 31;

    int qc0 = g_qcnt[0], qc1 = g_qcnt[1];
    int ngrp0 = (qc0 + 31) >> 5;
    int ngrp1 = (qc1 + 31) >> 5;
    int blk = blockIdx.x;
    int b, g, qc;
    if (blk < ngrp0)              { b = 0; g = blk;         qc = qc0; }
    else if (blk < ngrp0 + ngrp1) { b = 1; g = blk - ngrp0; qc = qc1; }
    else return;

    int idx = g * 32 + lane;
    if (idx >= qc) idx = qc - 1;           // duplicate tail: idempotent writes
    int qi = g_qidx[b][idx];
    int4 q = vc[qi];
    float qz = (float)q.y, qy = (float)q.z, qx = (float)q.w;

    const float4* kl = g_keys[b];
    int kc = g_kcnt[b];
    int ck = (kc + 7) >> 3;
    int ms = warp * ck;
    int me = ms + ck; if (me > kc) me = kc;

    // ---- pass 1: chunk-local max in dot-space ----
    float mxd = -3.0e38f;
    {
        int m = ms;
        for (; m + 3 < me; m += 4) {
            float4 k0 = kl[m], k1 = kl[m + 1], k2v = kl[m + 2], k3 = kl[m + 3];
            float d0 = DOTB(k0), d1 = DOTB(k1), d2 = DOTB(k2v), d3 = DOTB(k3);
            mxd = fmaxf(mxd, fmaxf(fmaxf(d0, d1), fmaxf(d2, d3)));
        }
        for (; m < me; m++) { float4 k0 = kl[m]; mxd = fmaxf(mxd, DOTB(k0)); }
    }
    smax[warp][lane] = mxd;
    __syncthreads();

    float gm = smax[0][lane];
    #pragma unroll
    for (int w = 1; w < 8; w++) gm = fmaxf(gm, smax[w][lane]);
    float mx  = gm / SQRT3;                 // == max(dot/sqrt3), monotone
    float thr = (mx - 88.0f) * SQRT3;       // conservative dot-space prefilter

    // ---- pass 2 (fused): chunk-local sum of exp + unnormalized weighted coords ----
    float sum = 0.0f, c0 = 0.0f, c1 = 0.0f, c2 = 0.0f;
    {
        int m = ms;
        for (; m + 3 < me; m += 4) {
            float4 k0 = kl[m], k1 = kl[m + 1], k2v = kl[m + 2], k3 = kl[m + 3];
            float d0 = DOTB(k0), d1 = DOTB(k1), d2 = DOTB(k2v), d3 = DOTB(k3);
            float md = fmaxf(fmaxf(d0, d1), fmaxf(d2, d3));
            if (md > thr) {                  // rare path
                float ds[4] = {d0, d1, d2, d3};
                float4 ks[4] = {k0, k1, k2v, k3};
                #pragma unroll
                for (int e = 0; e < 4; e++) {
                    float d = ds[e];
                    if (d > thr) {
                        float s = d / SQRT3;
                        float t2 = s - mx;
                        if (t2 > -80.0f) {
                            float a = expf(t2);
                            sum += a;
                            c0 = fmaf(a, ks[e].x, c0);
                            c1 = fmaf(a, ks[e].y, c1);
                            c2 = fmaf(a, ks[e].z, c2);
                        }
                    }
                }
            }
        }
        for (; m < me; m++) {
            float4 k0 = kl[m];
            float d = DOTB(k0);
            if (d > thr) {
                float s = d / SQRT3;
                float t2 = s - mx;
                if (t2 > -80.0f) {
                    float a = expf(t2);
                    sum += a;
                    c0 = fmaf(a, k0.x, c0);
                    c1 = fmaf(a, k0.y, c1);
                    c2 = fmaf(a, k0.z, c2);
                }
            }
        }
    }
    sacc[warp][lane] = make_float4(sum, c0, c1, c2);
    __syncthreads();

    // ---- warp 0: combine partials in fixed order; lane-parallel MLP + logistic ----
    if (warp == 0) {
        float S = 0, C0 = 0, C1 = 0, C2 = 0;
        #pragma unroll
        for (int w = 0; w < 8; w++) {
            float4 a = sacc[w][lane];
            S += a.x; C0 += a.y; C1 += a.z; C2 += a.w;
        }
        C0 /= S; C1 /= S; C2 /= S;
        float logit = 0.0f;
        #pragma unroll
        for (int j = 0; j < 32; j++) {
            float h = C0 * w1[j];
            h = fmaf(C1, w1[32 + j], h);
            h = fmaf(C2, w1[64 + j], h);
            h = h + b1[j];
            h = fmaxf(h, 0.0f);
            logit = fmaf(h, w2[j], logit);
        }
        logit = logit + b2[0];
        float impv = 0.5f + 0.5f * tanh_xla(0.5f * logit);
        imp_out[qi] = impv;
        // impv >= 0 => float bits monotone as unsigned; index breaks ties stably
        g_key64[qi] = ((u64)__float_as_uint(impv) << 13) | (u64)qi;
    }
}

// ---- rank: voxel-per-lane, key-broadcast, 8 chunks per block ----
__global__ __launch_bounds__(256) void rank_kernel(
    const float* __restrict__ imp,
    const int*   __restrict__ vc,
    const float* __restrict__ voxels,
    float*       __restrict__ out)
{
    __shared__ int scnt[8][32];
    int warp = threadIdx.x >> 5, lane = threadIdx.x & 31;
    int vbase = blockIdx.x * 32;

    u64 myk = g_key64[vbase + lane];
    const ulonglong2* k2 = (const ulonglong2*)g_key64;

    int js = warp * (NQ / 16);        // NQ/2 ulonglong2 over 8 warps = 512 each
    int je = js + (NQ / 16);
    int cnt = 0;
    #pragma unroll 4
    for (int j = js; j < je; j++) {
        ulonglong2 kk = k2[j];
        cnt += (int)(kk.x < myk) + (int)(kk.y < myk);
    }
    scnt[warp][lane] = cnt;
    __syncthreads();

    if (warp == 0) {
        int tot = 0;
        #pragma unroll
        for (int w = 0; w < 8; w++) tot += scnt[w][lane];

        #pragma unroll 4
        for (int i = 0; i < 32; i++) {
            int c = __shfl_sync(0xffffffffu, tot, i);
            if (c >= KEEP) {
                int row = c - KEEP;
                int q = vbase + i;
                if (lane < 20)
                    out[OFF_VOX + row * 20 + lane] = voxels[q * 20 + lane];
                if (lane < 4)
                    out[OFF_COORDS + row * 4 + lane] = (float)vc[q * 4 + lane];
                if (lane == 0)
                    out[OFF_KIMP + row] = imp[q];
            }
        }
    }
}

extern "C" void kernel_launch(void* const* d_in, const int* in_sizes, int n_in,
                              void* d_out, int out_size) {
    const int*   vc     = (const int*)d_in[0];
    const float* keys   = (const float*)d_in[1];
    const float* voxels = (const float*)d_in[2];
    const float* w1     = (const float*)d_in[3];
    const float* b1     = (const float*)d_in[4];
    const float* w2     = (const float*)d_in[5];
    const float* b2     = (const float*)d_in[6];
    float* out = (float*)d_out;
    float* imp = out + OFF_IMP;

    count_kernel<<<64, 256>>>((const int4*)vc, (const float4*)keys);
    scatter_kernel<<<64, 256>>>((const int4*)vc, (const float4*)keys);
    attn_kernel<<<258, 256>>>((const int4*)vc, w1, b1, w2, b2, imp);
    rank_kernel<<<NQ / 32, 256>>>(imp, vc, voxels, out);
}

// round 13
// speedup vs baseline: 1.3560x; 1.3560x over previous
#include <cuda_runtime.h>
#include <cuda_bf16.h>
#include <cstdint>

#define NQ 8192
#define NK 8192
#define KEEP 4096

// Concatenated float32 output offsets
#define OFF_COORDS 0
#define OFF_VOX    16384
#define OFF_KIMP   98304
#define OFF_IMP    102400

#define SQRT3 1.7320508075688772f

typedef unsigned int uint32;

// ---- persistent device scratch (allocation-free) ----
__device__ __align__(16) float4 g_keys[2][NK];  // (z,y,x,0) grouped by batch, stable order
__device__ int    g_kcnt[2];
__device__ int    g_qidx[2][NQ];                // query indices grouped by batch, stable
__device__ int    g_qcnt[2];
__device__ int    g_bc[64];                     // per-block batch-0 counts

// XLA EmitFastTanh (Eigen ptanh<float>) — exact coefficients, clamp, small-x path.
__device__ __forceinline__ float tanh_xla(float x) {
    float ax = fabsf(x);
    float xc = fminf(fmaxf(x, -7.90531110763549805f), 7.90531110763549805f);
    float x2 = xc * xc;
    float p = fmaf(x2, -2.76076847742355e-16f, 2.00018790482477e-13f);
    p = fmaf(x2, p, -8.60467152213735e-11f);
    p = fmaf(x2, p, 5.12229709037114e-08f);
    p = fmaf(x2, p, 1.48572235717979e-05f);
    p = fmaf(x2, p, 6.37261928875436e-04f);
    p = fmaf(x2, p, 4.89352455891786e-03f);
    p = xc * p;
    float q = fmaf(x2, 1.19825839466702e-06f, 1.18534705686654e-04f);
    q = fmaf(x2, q, 2.26843463243900e-03f);
    q = fmaf(x2, q, 4.89352518554385e-03f);
    float r = p / q;
    return (ax < 0.0004f) ? x : r;
}

// ---- partition phase 1: per-block batch-0 counts (64 blocks x 256 threads) ----
__global__ __launch_bounds__(256) void count_kernel(
    const int4* __restrict__ vc, const float4* __restrict__ keys)
{
    __shared__ int ws[8];
    int b = blockIdx.x, t = threadIdx.x;
    int flag;
    if (b < 32) flag = (keys[b * 256 + t].x == 0.0f) ? 1 : 0;
    else        flag = (vc[(b - 32) * 256 + t].x == 0) ? 1 : 0;
    unsigned bal = __ballot_sync(0xffffffffu, flag);
    if ((t & 31) == 0) ws[t >> 5] = __popc(bal);
    __syncthreads();
    if (t == 0) {
        int s = 0;
        #pragma unroll
        for (int i = 0; i < 8; i++) s += ws[i];
        g_bc[b] = s;
    }
}

// ---- partition phase 2: stable scatter (64 blocks x 256 threads) ----
__global__ __launch_bounds__(256) void scatter_kernel(
    const int4* __restrict__ vc, const float4* __restrict__ keys)
{
    __shared__ int ws[8];
    __shared__ int s_pre0, s_tot0;
    int b = blockIdx.x, t = threadIdx.x;
    bool isKey = (b < 32);
    int c = isKey ? b : b - 32;
    int grp = isKey ? 0 : 32;

    if (t < 32) {
        int v = g_bc[grp + t];
        int x = v;
        #pragma unroll
        for (int o = 1; o < 32; o <<= 1) {
            int y = __shfl_up_sync(0xffffffffu, x, o);
            if (t >= o) x += y;
        }
        if (t == c)  s_pre0 = x - v;
        if (t == 31) s_tot0 = x;
    }
    __syncthreads();

    int i = c * 256 + t;
    int flag;
    float4 kv; int4 qv;
    if (isKey) { kv = keys[i]; flag = (kv.x == 0.0f) ? 1 : 0; }
    else       { qv = vc[i];   flag = (qv.x == 0) ? 1 : 0; }

    unsigned bal = __ballot_sync(0xffffffffu, flag);
    int lane = t & 31, w = t >> 5;
    int lpre = __popc(bal & ((1u << lane) - 1u));
    if (lane == 0) ws[w] = __popc(bal);
    __syncthreads();
    int wpre = 0;
    for (int j = 0; j < w; j++) wpre += ws[j];

    int pos0 = s_pre0 + wpre + lpre;
    int pos1 = i - pos0;
    if (isKey) {
        int bb = flag ? 0 : 1;
        int pp = flag ? pos0 : pos1;
        g_keys[bb][pp] = make_float4(kv.y, kv.z, kv.w, 0.0f);  // (z,y,x)
        if (t == 0 && c == 0) { g_kcnt[0] = s_tot0; g_kcnt[1] = NK - s_tot0; }
    } else {
        if (flag) g_qidx[0][pos0] = i; else g_qidx[1][pos1] = i;
        if (t == 0 && c == 0) { g_qcnt[0] = s_tot0; g_qcnt[1] = NQ - s_tot0; }
    }
}

// ---- attention: query-per-lane; 8 warps sweep 8 key-chunks via warp-private
//      SMEM tiles with uniform LDS; fixed-order smem combine (as R11). ----
#define DOTB(k) (fmaf(qx, (k).z, fmaf(qy, (k).y, qz * (k).x)))
#define TILE 256

__global__ __launch_bounds__(256) void attn_kernel(
    const int4*  __restrict__ vc,
    const float* __restrict__ w1,
    const float* __restrict__ b1,
    const float* __restrict__ w2,
    const float* __restrict__ b2,
    float*       __restrict__ imp_out)
{
    __shared__ float4 stile[8][TILE];
    __shared__ float  smax[8][32];
    __shared__ float4 sacc[8][32];

    int warp = threadIdx.x >> 5, lane = threadIdx.x & 31;

    int qc0 = g_qcnt[0], qc1 = g_qcnt[1];
    int ngrp0 = (qc0 + 31) >> 5;
    int ngrp1 = (qc1 + 31) >> 5;
    int blk = blockIdx.x;
    int b, g, qc;
    if (blk < ngrp0)              { b = 0; g = blk;         qc = qc0; }
    else if (blk < ngrp0 + ngrp1) { b = 1; g = blk - ngrp0; qc = qc1; }
    else return;

    int idx = g * 32 + lane;
    if (idx >= qc) idx = qc - 1;           // duplicate tail: idempotent writes
    int qi = g_qidx[b][idx];
    int4 q = vc[qi];
    float qz = (float)q.y, qy = (float)q.z, qx = (float)q.w;

    const float4* kl = g_keys[b];
    int kc = g_kcnt[b];
    int ck = (kc + 7) >> 3;
    int ms = warp * ck;
    int me = ms + ck; if (me > kc) me = kc;

    // ---- pass 1: chunk-local max in dot-space, smem tiles, 4 accumulators ----
    float m0 = -3.0e38f, m1 = -3.0e38f, m2 = -3.0e38f, m3 = -3.0e38f;
    for (int ts = ms; ts < me; ts += TILE) {
        int n = me - ts; if (n > TILE) n = TILE;
        for (int r = lane; r < n; r += 32) stile[warp][r] = kl[ts + r];
        __syncwarp();
        int j = 0;
        for (; j + 3 < n; j += 4) {
            float4 k0 = stile[warp][j],     k1 = stile[warp][j + 1];
            float4 k2 = stile[warp][j + 2], k3 = stile[warp][j + 3];
            m0 = fmaxf(m0, DOTB(k0)); m1 = fmaxf(m1, DOTB(k1));
            m2 = fmaxf(m2, DOTB(k2)); m3 = fmaxf(m3, DOTB(k3));
        }
        for (; j < n; j++) { float4 k0 = stile[warp][j]; m0 = fmaxf(m0, DOTB(k0)); }
        __syncwarp();
    }
    smax[warp][lane] = fmaxf(fmaxf(m0, m1), fmaxf(m2, m3));
    __syncthreads();

    float gm = smax[0][lane];
    #pragma unroll
    for (int w = 1; w < 8; w++) gm = fmaxf(gm, smax[w][lane]);
    float mx  = gm / SQRT3;                 // == max(dot/sqrt3), monotone
    float thr = (mx - 88.0f) * SQRT3;       // conservative dot-space prefilter

    // ---- pass 2 (fused): chunk-local sum of exp + unnormalized weighted coords ----
    float sum = 0.0f, c0 = 0.0f, c1 = 0.0f, c2 = 0.0f;
    for (int ts = ms; ts < me; ts += TILE) {
        int n = me - ts; if (n > TILE) n = TILE;
        for (int r = lane; r < n; r += 32) stile[warp][r] = kl[ts + r];
        __syncwarp();
        int j = 0;
        for (; j + 3 < n; j += 4) {
            float4 k0 = stile[warp][j],     k1 = stile[warp][j + 1];
            float4 k2 = stile[warp][j + 2], k3 = stile[warp][j + 3];
            float d0 = DOTB(k0), d1 = DOTB(k1), d2 = DOTB(k2), d3 = DOTB(k3);
            float md = fmaxf(fmaxf(d0, d1), fmaxf(d2, d3));
            if (md > thr) {                  // rare path
                float ds[4] = {d0, d1, d2, d3};
                float4 ks[4] = {k0, k1, k2, k3};
                #pragma unroll
                for (int e = 0; e < 4; e++) {
                    float d = ds[e];
                    if (d > thr) {
                        float s = d / SQRT3;
                        float t2 = s - mx;
                        if (t2 > -80.0f) {
                            float a = expf(t2);
                            sum += a;
                            c0 = fmaf(a, ks[e].x, c0);
                            c1 = fmaf(a, ks[e].y, c1);
                            c2 = fmaf(a, ks[e].z, c2);
                        }
                    }
                }
            }
        }
        for (; j < n; j++) {
            float4 k0 = stile[warp][j];
            float d = DOTB(k0);
            if (d > thr) {
                float s = d / SQRT3;
                float t2 = s - mx;
                if (t2 > -80.0f) {
                    float a = expf(t2);
                    sum += a;
                    c0 = fmaf(a, k0.x, c0);
                    c1 = fmaf(a, k0.y, c1);
                    c2 = fmaf(a, k0.z, c2);
                }
            }
        }
        __syncwarp();
    }
    sacc[warp][lane] = make_float4(sum, c0, c1, c2);
    __syncthreads();

    // ---- warp 0: combine partials in fixed order; lane-parallel MLP + logistic ----
    if (warp == 0) {
        float S = 0, C0 = 0, C1 = 0, C2 = 0;
        #pragma unroll
        for (int w = 0; w < 8; w++) {
            float4 a = sacc[w][lane];
            S += a.x; C0 += a.y; C1 += a.z; C2 += a.w;
        }
        C0 /= S; C1 /= S; C2 /= S;
        float logit = 0.0f;
        #pragma unroll
        for (int j = 0; j < 32; j++) {
            float h = C0 * w1[j];
            h = fmaf(C1, w1[32 + j], h);
            h = fmaf(C2, w1[64 + j], h);
            h = h + b1[j];
            h = fmaxf(h, 0.0f);
            logit = fmaf(h, w2[j], logit);
        }
        logit = logit + b2[0];
        imp_out[qi] = 0.5f + 0.5f * tanh_xla(0.5f * logit);
    }
}

// ---- rank: warp-per-voxel, split-loop stable counting on float bits ----
// rank(i) = #{j : v_j < v_i} + #{j < i : v_j == v_i}
//  region A (j<i): count v<=my ; region B (j>=i): count v<my (j==i adds 0).
// imp >= 0 always, so u32 bit compare == float compare; equal bits == equal floats.
__global__ __launch_bounds__(256) void rank_kernel(
    const float* __restrict__ imp,
    const int*   __restrict__ vc,
    const float* __restrict__ voxels,
    float*       __restrict__ out)
{
    int warp = (blockIdx.x * blockDim.x + threadIdx.x) >> 5;   // voxel index i
    int lane = threadIdx.x & 31;
    int i = warp;

    const uint32* ib  = (const uint32*)imp;
    const uint4*  ib4 = (const uint4*)imp;
    uint32 my = ib[i];

    int tA = i >> 7;           // iteration t covers j in [128t, 128t+128)
    int cnt = 0;

    // region A: all j < i
    #pragma unroll 4
    for (int t = 0; t < tA; t++) {
        uint4 v = ib4[t * 32 + lane];
        cnt += (int)(v.x <= my) + (int)(v.y <= my) + (int)(v.z <= my) + (int)(v.w <= my);
    }
    // boundary iteration t = tA (contains j == i)
    {
        uint4 v = ib4[tA * 32 + lane];
        int j = tA * 128 + lane * 4;
        cnt += (j + 0 < i) ? (int)(v.x <= my) : (int)(v.x < my);
        cnt += (j + 1 < i) ? (int)(v.y <= my) : (int)(v.y < my);
        cnt += (j + 2 < i) ? (int)(v.z <= my) : (int)(v.z < my);
        cnt += (j + 3 < i) ? (int)(v.w <= my) : (int)(v.w < my);
    }
    // region B: all j > i
    #pragma unroll 4
    for (int t = tA + 1; t < NQ / 128; t++) {
        uint4 v = ib4[t * 32 + lane];
        cnt += (int)(v.x < my) + (int)(v.y < my) + (int)(v.z < my) + (int)(v.w < my);
    }

    #pragma unroll
    for (int o = 16; o; o >>= 1) cnt += __shfl_xor_sync(0xffffffffu, cnt, o);

    if (cnt >= KEEP) {
        int row = cnt - KEEP;
        if (lane < 20)
            out[OFF_VOX + row * 20 + lane] = voxels[i * 20 + lane];
        if (lane < 4)
            out[OFF_COORDS + row * 4 + lane] = (float)vc[i * 4 + lane];
        if (lane == 0)
            out[OFF_KIMP + row] = imp[i];
    }
}

extern "C" void kernel_launch(void* const* d_in, const int* in_sizes, int n_in,
                              void* d_out, int out_size) {
    const int*   vc     = (const int*)d_in[0];
    const float* keys   = (const float*)d_in[1];
    const float* voxels = (const float*)d_in[2];
    const float* w1     = (const float*)d_in[3];
    const float* b1     = (const float*)d_in[4];
    const float* w2     = (const float*)d_in[5];
    const float* b2     = (const float*)d_in[6];
    float* out = (float*)d_out;
    float* imp = out + OFF_IMP;

    count_kernel<<<64, 256>>>((const int4*)vc, (const float4*)keys);
    scatter_kernel<<<64, 256>>>((const int4*)vc, (const float4*)keys);
    attn_kernel<<<258, 256>>>((const int4*)vc, w1, b1, w2, b2, imp);
    rank_kernel<<<NQ / 8, 256>>>(imp, vc, voxels, out);
}

// round 16
// speedup vs baseline: 1.9829x; 1.4623x over previous
#include <cuda_runtime.h>
#include <cuda_bf16.h>
#include <cstdint>

#define NQ 8192
#define NK 8192
#define KEEP 4096

// Concatenated float32 output offsets
#define OFF_COORDS 0
#define OFF_VOX    16384
#define OFF_KIMP   98304
#define OFF_IMP    102400

#define SQRT3 1.7320508075688772f

typedef unsigned long long u64;
typedef unsigned int u32;

// ---- persistent device scratch (allocation-free) ----
__device__ __align__(16) float g_kz[2][NK];   // key z-coord, grouped by batch, stable order
__device__ __align__(16) float g_ky[2][NK];   // key y-coord
__device__ __align__(16) float g_kx[2][NK];   // key x-coord
__device__ int    g_kcnt[2];
__device__ int    g_qidx[2][NQ];              // query indices grouped by batch, stable
__device__ int    g_qcnt[2];
__device__ int    g_bc[64];                   // per-block batch-0 counts

// ---- packed f32x2 helpers (IEEE per-lane, bit-identical to scalar) ----
__device__ __forceinline__ u64 mul2(u64 a, u64 b) {
    u64 d; asm("mul.rn.f32x2 %0, %1, %2;" : "=l"(d) : "l"(a), "l"(b)); return d;
}
__device__ __forceinline__ u64 fma2(u64 a, u64 b, u64 c) {
    u64 d; asm("fma.rn.f32x2 %0, %1, %2, %3;" : "=l"(d) : "l"(a), "l"(b), "l"(c)); return d;
}
__device__ __forceinline__ u64 pack2(float v) {
    u64 d; asm("mov.b64 %0, {%1, %1};" : "=l"(d) : "f"(v)); return d;
}
__device__ __forceinline__ float2 unpack2(u64 v) {
    float2 f; asm("mov.b64 {%0, %1}, %2;" : "=f"(f.x), "=f"(f.y) : "l"(v)); return f;
}

// XLA EmitFastTanh (Eigen ptanh<float>) — exact coefficients, clamp, small-x path.
__device__ __forceinline__ float tanh_xla(float x) {
    float ax = fabsf(x);
    float xc = fminf(fmaxf(x, -7.90531110763549805f), 7.90531110763549805f);
    float x2 = xc * xc;
    float p = fmaf(x2, -2.76076847742355e-16f, 2.00018790482477e-13f);
    p = fmaf(x2, p, -8.60467152213735e-11f);
    p = fmaf(x2, p, 5.12229709037114e-08f);
    p = fmaf(x2, p, 1.48572235717979e-05f);
    p = fmaf(x2, p, 6.37261928875436e-04f);
    p = fmaf(x2, p, 4.89352455891786e-03f);
    p = xc * p;
    float q = fmaf(x2, 1.19825839466702e-06f, 1.18534705686654e-04f);
    q = fmaf(x2, q, 2.26843463243900e-03f);
    q = fmaf(x2, q, 4.89352518554385e-03f);
    float r = p / q;
    return (ax < 0.0004f) ? x : r;
}

// ---- partition phase 1: per-block batch-0 counts (64 blocks x 256 threads) ----
__global__ __launch_bounds__(256) void count_kernel(
    const int4* __restrict__ vc, const float4* __restrict__ keys)
{
    __shared__ int ws[8];
    int b = blockIdx.x, t = threadIdx.x;
    int flag;
    if (b < 32) flag = (keys[b * 256 + t].x == 0.0f) ? 1 : 0;
    else        flag = (vc[(b - 32) * 256 + t].x == 0) ? 1 : 0;
    unsigned bal = __ballot_sync(0xffffffffu, flag);
    if ((t & 31) == 0) ws[t >> 5] = __popc(bal);
    __syncthreads();
    if (t == 0) {
        int s = 0;
        #pragma unroll
        for (int i = 0; i < 8; i++) s += ws[i];
        g_bc[b] = s;
    }
}

// ---- partition phase 2: stable scatter to SoA (64 blocks x 256 threads) ----
__global__ __launch_bounds__(256) void scatter_kernel(
    const int4* __restrict__ vc, const float4* __restrict__ keys)
{
    __shared__ int ws[8];
    __shared__ int s_pre0, s_tot0;
    int b = blockIdx.x, t = threadIdx.x;
    bool isKey = (b < 32);
    int c = isKey ? b : b - 32;
    int grp = isKey ? 0 : 32;

    if (t < 32) {
        int v = g_bc[grp + t];
        int x = v;
        #pragma unroll
        for (int o = 1; o < 32; o <<= 1) {
            int y = __shfl_up_sync(0xffffffffu, x, o);
            if (t >= o) x += y;
        }
        if (t == c)  s_pre0 = x - v;
        if (t == 31) s_tot0 = x;
    }
    __syncthreads();

    int i = c * 256 + t;
    int flag;
    float4 kv; int4 qv;
    if (isKey) { kv = keys[i]; flag = (kv.x == 0.0f) ? 1 : 0; }
    else       { qv = vc[i];   flag = (qv.x == 0) ? 1 : 0; }

    unsigned bal = __ballot_sync(0xffffffffu, flag);
    int lane = t & 31, w = t >> 5;
    int lpre = __popc(bal & ((1u << lane) - 1u));
    if (lane == 0) ws[w] = __popc(bal);
    __syncthreads();
    int wpre = 0;
    for (int j = 0; j < w; j++) wpre += ws[j];

    int pos0 = s_pre0 + wpre + lpre;
    int pos1 = i - pos0;
    if (isKey) {
        int bb = flag ? 0 : 1;
        int pp = flag ? pos0 : pos1;
        g_kz[bb][pp] = kv.y;
        g_ky[bb][pp] = kv.z;
        g_kx[bb][pp] = kv.w;
        if (t == 0 && c == 0) { g_kcnt[0] = s_tot0; g_kcnt[1] = NK - s_tot0; }
    } else {
        if (flag) g_qidx[0][pos0] = i; else g_qidx[1][pos1] = i;
        if (t == 0 && c == 0) { g_qcnt[0] = s_tot0; g_qcnt[1] = NQ - s_tot0; }
    }
}

// ---- attention: 2 same-batch queries per warp; SoA keys; packed f32x2 dots ----
#define QPW 2

__global__ __launch_bounds__(256) void attn_kernel(
    const int4*  __restrict__ vc,
    const float* __restrict__ w1,
    const float* __restrict__ b1,
    const float* __restrict__ w2,
    const float* __restrict__ b2,
    float*       __restrict__ imp_out)
{
    int warp = (blockIdx.x * blockDim.x + threadIdx.x) >> 5;
    int lane = threadIdx.x & 31;

    int qc0 = g_qcnt[0], qc1 = g_qcnt[1];
    int ngrp0 = (qc0 + QPW - 1) / QPW;
    int ngrp1 = (qc1 + QPW - 1) / QPW;
    int b, g, qc;
    if (warp < ngrp0)              { b = 0; g = warp;         qc = qc0; }
    else if (warp < ngrp0 + ngrp1) { b = 1; g = warp - ngrp0; qc = qc1; }
    else return;
    if (qc == 0) return;

    int qi[QPW];
    float qzs[QPW], qys[QPW], qxs[QPW];
    u64 qz2[QPW], qy2[QPW], qx2[QPW];
    #pragma unroll
    for (int i = 0; i < QPW; i++) {
        int idx = QPW * g + i;
        qi[i] = g_qidx[b][idx < qc ? idx : qc - 1];
        int4 q = vc[qi[i]];
        qzs[i] = (float)q.y; qys[i] = (float)q.z; qxs[i] = (float)q.w;
        qz2[i] = pack2(qzs[i]); qy2[i] = pack2(qys[i]); qx2[i] = pack2(qxs[i]);
    }

    const ulonglong2* z2 = (const ulonglong2*)g_kz[b];
    const ulonglong2* y2 = (const ulonglong2*)g_ky[b];
    const ulonglong2* x2 = (const ulonglong2*)g_kx[b];
    const float* kzs = g_kz[b];
    const float* kys = g_ky[b];
    const float* kxs = g_kx[b];
    int kc = g_kcnt[b];
    int nfull = kc & ~127;          // 128 keys per warp-iteration

    // ---- pass 1: max in dot-space (exact; order-free) ----
    float mxd[QPW];
    #pragma unroll
    for (int i = 0; i < QPW; i++) mxd[i] = -3.0e38f;

    for (int base = 0; base < nfull; base += 128) {
        int m2 = (base >> 2) + lane;          // ulonglong2 index: 4 keys
        ulonglong2 zz = z2[m2], yy = y2[m2], xx = x2[m2];
        #pragma unroll
        for (int i = 0; i < QPW; i++) {
            u64 d01 = fma2(qx2[i], xx.x, fma2(qy2[i], yy.x, mul2(qz2[i], zz.x)));
            u64 d23 = fma2(qx2[i], xx.y, fma2(qy2[i], yy.y, mul2(qz2[i], zz.y)));
            float2 a = unpack2(d01), c = unpack2(d23);
            mxd[i] = fmaxf(mxd[i],
                     fmaxf(fmaxf(a.x, a.y), fmaxf(c.x, c.y)));
        }
    }
    for (int m = nfull + lane; m < kc; m += 32) {
        float kz = kzs[m], ky = kys[m], kx = kxs[m];
        #pragma unroll
        for (int i = 0; i < QPW; i++) {
            float d = fmaf(qxs[i], kx, fmaf(qys[i], ky, qzs[i] * kz));
            mxd[i] = fmaxf(mxd[i], d);
        }
    }
    #pragma unroll
    for (int o = 16; o; o >>= 1)
        #pragma unroll
        for (int i = 0; i < QPW; i++)
            mxd[i] = fmaxf(mxd[i], __shfl_xor_sync(0xffffffffu, mxd[i], o));

    float mx[QPW], thr[QPW];
    #pragma unroll
    for (int i = 0; i < QPW; i++) {
        mx[i]  = mxd[i] / SQRT3;              // == max(dot/sqrt3), monotone
        thr[i] = (mx[i] - 88.0f) * SQRT3;     // conservative dot-space prefilter
    }

    // ---- pass 2 (fused): sum of exp AND unnormalized weighted coords ----
    float sum[QPW], c0[QPW], c1[QPW], c2[QPW];
    #pragma unroll
    for (int i = 0; i < QPW; i++) { sum[i] = 0; c0[i] = 0; c1[i] = 0; c2[i] = 0; }

    for (int base = 0; base < nfull; base += 128) {
        int m2 = (base >> 2) + lane;
        ulonglong2 zz = z2[m2], yy = y2[m2], xx = x2[m2];
        #pragma unroll
        for (int i = 0; i < QPW; i++) {
            u64 d01 = fma2(qx2[i], xx.x, fma2(qy2[i], yy.x, mul2(qz2[i], zz.x)));
            u64 d23 = fma2(qx2[i], xx.y, fma2(qy2[i], yy.y, mul2(qz2[i], zz.y)));
            float2 a = unpack2(d01), c = unpack2(d23);
            float md = fmaxf(fmaxf(a.x, a.y), fmaxf(c.x, c.y));
            if (md > thr[i]) {                 // rare path
                float ds[4] = {a.x, a.y, c.x, c.y};
                float2 kzp0 = unpack2(zz.x), kzp1 = unpack2(zz.y);
                float2 kyp0 = unpack2(yy.x), kyp1 = unpack2(yy.y);
                float2 kxp0 = unpack2(xx.x), kxp1 = unpack2(xx.y);
                float kzv[4] = {kzp0.x, kzp0.y, kzp1.x, kzp1.y};
                float kyv[4] = {kyp0.x, kyp0.y, kyp1.x, kyp1.y};
                float kxv[4] = {kxp0.x, kxp0.y, kxp1.x, kxp1.y};
                #pragma unroll
                for (int e = 0; e < 4; e++) {
                    float d = ds[e];
                    if (d > thr[i]) {
                        float s = d / SQRT3;
                        float t2 = s - mx[i];
                        if (t2 > -80.0f) {
                            float aa = expf(t2);
                            sum[i] += aa;
                            c0[i] = fmaf(aa, kzv[e], c0[i]);
                            c1[i] = fmaf(aa, kyv[e], c1[i]);
                            c2[i] = fmaf(aa, kxv[e], c2[i]);
                        }
                    }
                }
            }
        }
    }
    for (int m = nfull + lane; m < kc; m += 32) {
        float kz = kzs[m], ky = kys[m], kx = kxs[m];
        #pragma unroll
        for (int i = 0; i < QPW; i++) {
            float d = fmaf(qxs[i], kx, fmaf(qys[i], ky, qzs[i] * kz));
            if (d > thr[i]) {
                float s = d / SQRT3;
                float t2 = s - mx[i];
                if (t2 > -80.0f) {
                    float aa = expf(t2);
                    sum[i] += aa;
                    c0[i] = fmaf(aa, kz, c0[i]);
                    c1[i] = fmaf(aa, ky, c1[i]);
                    c2[i] = fmaf(aa, kx, c2[i]);
                }
            }
        }
    }
    #pragma unroll
    for (int o = 16; o; o >>= 1)
        #pragma unroll
        for (int i = 0; i < QPW; i++) {
            sum[i] += __shfl_xor_sync(0xffffffffu, sum[i], o);
            c0[i]  += __shfl_xor_sync(0xffffffffu, c0[i], o);
            c1[i]  += __shfl_xor_sync(0xffffffffu, c1[i], o);
            c2[i]  += __shfl_xor_sync(0xffffffffu, c2[i], o);
        }

    // ---- MLP + logistic ----
    #pragma unroll
    for (int i = 0; i < QPW; i++) {
        if (lane == i) {
            float C0 = c0[i] / sum[i];
            float C1 = c1[i] / sum[i];
            float C2 = c2[i] / sum[i];
            float logit = 0.0f;
            #pragma unroll
            for (int j = 0; j < 32; j++) {
                float h = C0 * w1[j];
                h = fmaf(C1, w1[32 + j], h);
                h = fmaf(C2, w1[64 + j], h);
                h = h + b1[j];
                h = fmaxf(h, 0.0f);
                logit = fmaf(h, w2[j], logit);
            }
            logit = logit + b2[0];
            imp_out[qi[i]] = 0.5f + 0.5f * tanh_xla(0.5f * logit);
        }
    }
}

// ---- rank: warp per 2 voxels; split-loop stable counting on float bits ----
// rank(i) = #{j<i : v_j <= v_i} + #{j>i : v_j < v_i}  (exact stable-ascending rank)
// imp >= 0, so u32 bit compare == float compare; equal bits == equal floats.
// i0 = 2w (even) and i1 = i0+1 share the same boundary iteration (i0>>7 == i1>>7).
__global__ __launch_bounds__(256) void rank_kernel(
    const float* __restrict__ imp,
    const int*   __restrict__ vc,
    const float* __restrict__ voxels,
    float*       __restrict__ out)
{
    int warp = (blockIdx.x * blockDim.x + threadIdx.x) >> 5;
    int lane = threadIdx.x & 31;
    if (warp >= NQ / 2) return;
    int i0 = 2 * warp, i1 = i0 + 1;

    const u32*   ib  = (const u32*)imp;
    const uint4* ib4 = (const uint4*)imp;
    u32 my0 = ib[i0], my1 = ib[i1];

    int tA = i0 >> 7;            // iteration t covers j in [128t, 128t+128)
    int cnt0 = 0, cnt1 = 0;

    // region A: all j < i0 (and < i1)
    #pragma unroll 4
    for (int t = 0; t < tA; t++) {
        uint4 v = ib4[t * 32 + lane];
        cnt0 += (int)(v.x <= my0) + (int)(v.y <= my0) + (int)(v.z <= my0) + (int)(v.w <= my0);
        cnt1 += (int)(v.x <= my1) + (int)(v.y <= my1) + (int)(v.z <= my1) + (int)(v.w <= my1);
    }
    // boundary iteration t = tA (contains j == i0 and j == i1)
    {
        uint4 v = ib4[tA * 32 + lane];
        int j = tA * 128 + lane * 4;
        u32 e[4] = {v.x, v.y, v.z, v.w};
        #pragma unroll
        for (int k = 0; k < 4; k++) {
            cnt0 += (j + k < i0) ? (int)(e[k] <= my0) : (int)(e[k] < my0);
            cnt1 += (j + k < i1) ? (int)(e[k] <= my1) : (int)(e[k] < my1);
        }
    }
    // region B: all j > i1 (and > i0)
    #pragma unroll 4
    for (int t = tA + 1; t < NQ / 128; t++) {
        uint4 v = ib4[t * 32 + lane];
        cnt0 += (int)(v.x < my0) + (int)(v.y < my0) + (int)(v.z < my0) + (int)(v.w < my0);
        cnt1 += (int)(v.x < my1) + (int)(v.y < my1) + (int)(v.z < my1) + (int)(v.w < my1);
    }

    #pragma unroll
    for (int o = 16; o; o >>= 1) {
        cnt0 += __shfl_xor_sync(0xffffffffu, cnt0, o);
        cnt1 += __shfl_xor_sync(0xffffffffu, cnt1, o);
    }

    if (cnt0 >= KEEP) {
        int row = cnt0 - KEEP;
        if (lane < 20) out[OFF_VOX + row * 20 + lane] = voxels[i0 * 20 + lane];
        if (lane < 4)  out[OFF_COORDS + row * 4 + lane] = (float)vc[i0 * 4 + lane];
        if (lane == 0) out[OFF_KIMP + row] = imp[i0];
    }
    if (cnt1 >= KEEP) {
        int row = cnt1 - KEEP;
        if (lane < 20) out[OFF_VOX + row * 20 + lane] = voxels[i1 * 20 + lane];
        if (lane < 4)  out[OFF_COORDS + row * 4 + lane] = (float)vc[i1 * 4 + lane];
        if (lane == 0) out[OFF_KIMP + row] = imp[i1];
    }
}

extern "C" void kernel_launch(void* const* d_in, const int* in_sizes, int n_in,
                              void* d_out, int out_size) {
    const int*   vc     = (const int*)d_in[0];
    const float* keys   = (const float*)d_in[1];
    const float* voxels = (const float*)d_in[2];
    const float* w1     = (const float*)d_in[3];
    const float* b1     = (const float*)d_in[4];
    const float* w2     = (const float*)d_in[5];
    const float* b2     = (const float*)d_in[6];
    float* out = (float*)d_out;
    float* imp = out + OFF_IMP;

    count_kernel<<<64, 256>>>((const int4*)vc, (const float4*)keys);
    scatter_kernel<<<64, 256>>>((const int4*)vc, (const float4*)keys);
    attn_kernel<<<(NQ / QPW / 8) + 2, 256>>>((const int4*)vc, w1, b1, w2, b2, imp);
    rank_kernel<<<NQ / 2 / 8, 256>>>(imp, vc, voxels, out);
}